// round 16
// baseline (speedup 1.0000x reference)
#include <cuda_runtime.h>
#include <cuda_bf16.h>
#include <cuda_fp16.h>
#include <cstdint>
#include <math.h>

// Problem constants
#define B_   4
#define NA_  64
#define T_   128
#define D_   128
#define H_   8
#define DH_  16
#define L_   3
#define DFF_ 512
#define E_   65536
#define NN_  (T_ * NA_)        // 8192
#define R_   (B_ * NA_ * T_)   // 32768 rows
#define EPSV 1e-5f

// ---------------- scratch (device globals) ---------------------------------------
__device__ __align__(256) float d_x   [R_ * D_];
__device__ __align__(256) float d_oute[R_ * D_];
__device__ __align__(256) float d_qkv [R_ * 384];
__device__ __align__(256) float d_h1  [R_ * D_];
__device__ __align__(256) float d_s   [B_ * NN_];
__device__ __align__(256) float d_g   [B_ * NN_];
__device__ double d_stats[2];

// fp16 activations (single term)
__device__ __align__(256) __half d_oute_h[R_ * D_];
__device__ __align__(256) __half d_oh[R_ * D_];
__device__ __align__(256) __half d_h1h[R_ * D_];
__device__ __align__(256) __half d_ffh[R_ * DFF_];

// fp16 transposed weights ([N][K])
#define W_TOT 589824
__device__ __align__(256) __half d_wh[W_TOT];
__device__ __align__(256) float d_bqkv[L_ * 384];

// ---------------- helpers --------------------------------------------------------
__device__ __forceinline__ uint32_t smem_u32(const void* p) {
    uint32_t a;
    asm("{ .reg .u64 t; cvta.to.shared.u64 t, %1; cvt.u32.u64 %0, t; }" : "=r"(a) : "l"(p));
    return a;
}
__device__ __forceinline__ void cp16(uint32_t saddr, const void* gptr) {
    asm volatile("cp.async.cg.shared.global [%0], [%1], 16;" :: "r"(saddr), "l"(gptr));
}
#define CP_COMMIT() asm volatile("cp.async.commit_group;" ::: "memory")
#define CP_WAIT(n)  asm volatile("cp.async.wait_group %0;" :: "n"(n) : "memory")

#define LDSM_X4(r, addr) \
    asm volatile("ldmatrix.sync.aligned.m8n8.x4.shared.b16 {%0,%1,%2,%3}, [%4];" \
        : "=r"((r)[0]), "=r"((r)[1]), "=r"((r)[2]), "=r"((r)[3]) : "r"(addr))

__device__ __forceinline__ uint32_t pack_f16(float a, float b) {
    __half2 h = __floats2half2_rn(a, b);
    return *(uint32_t*)&h;
}

__device__ __forceinline__ void mma_f16(float* c, const uint32_t* a,
                                        uint32_t b0, uint32_t b1) {
    asm volatile(
        "mma.sync.aligned.m16n8k16.row.col.f32.f16.f16.f32 "
        "{%0,%1,%2,%3}, {%4,%5,%6,%7}, {%8,%9}, {%0,%1,%2,%3};"
        : "+f"(c[0]), "+f"(c[1]), "+f"(c[2]), "+f"(c[3])
        : "r"(a[0]), "r"(a[1]), "r"(a[2]), "r"(a[3]), "r"(b0), "r"(b1));
}

#define SAB 40
#define SBB 136

// 8-MMA group over a p-pair (RAW distance 8)
#define MMA_GROUP(accbase, af, bhf2)                                               \
    do {                                                                            \
        _Pragma("unroll")                                                           \
        for (int pi = 0; pi < 2; pi++)                                              \
            _Pragma("unroll")                                                       \
            for (int hf = 0; hf < 2; hf++)                                          \
                _Pragma("unroll")                                                   \
                for (int mt = 0; mt < 2; mt++)                                      \
                    mma_f16(acc[mt][(accbase) + 2 * pi + hf], (af)[mt],             \
                            (bhf2)[pi][2 * hf], (bhf2)[pi][2 * hf + 1]);            \
    } while (0)

// ================= persistent-B GEMM (K=128), single-term fp16 ==================
#define PG_B_ELEMS (128 * SBB)                 // 17408
#define PG_A_ELEMS (128 * SAB)                 // 5120
#define PG_A_OFF   (PG_B_ELEMS)
#define PG_LN_OFF  (PG_A_OFF + 2 * PG_A_ELEMS) // 27648 elems
#define PG_SMEM    ((PG_LN_OFF) * 2 + 2048)    // 57344 bytes -> 3 CTAs/SM

template <int MT, bool LN>
__global__ void __launch_bounds__(256, 3)
pgemm_kernel(const __half* __restrict__ Ahg,
             const __half* __restrict__ Bg,
             const float* __restrict__ bias,
             float* __restrict__ Cf,
             __half* __restrict__ Ch,
             int N, int relu,
             const float* __restrict__ resid,
             const float* __restrict__ lng, const float* __restrict__ lnb)
{
    extern __shared__ uint16_t sm[];
    uint16_t* Bh = sm;
    uint16_t* Ast = sm + PG_A_OFF;
    float* pS = (float*)(sm + PG_LN_OFF);
    float* pQ = pS + 256;

    int tid  = threadIdx.x;
    int wid  = tid >> 5;
    int lane = tid & 31;
    int g    = lane >> 2;
    int tg   = lane & 3;
    int lr   = lane & 7;
    int seg  = lane >> 3;
    int warp_m = wid & 3;
    int warp_n = wid >> 2;
    int bn0 = blockIdx.x * 128;
    int bm0 = blockIdx.y * (MT << 7);

    // ---- load full B tile via cp.async ----
    {
        const uint16_t* bh = (const uint16_t*)Bg + (size_t)bn0 * 128;
#pragma unroll
        for (int it = 0; it < 8; it++) {
            int idx = it * 256 + tid;
            int row = idx >> 4, ch = idx & 15;
            cp16(smem_u32(Bh + row * SBB + ch * 8), bh + row * 128 + ch * 8);
        }
    }

    int lrow = tid >> 2;
    int lch  = tid & 3;

    const uint16_t* ahg = (const uint16_t*)Ahg;

    constexpr int NC = MT << 2;

    {
        uint16_t* dh = Ast;
        const uint16_t* ah = ahg + (size_t)bm0 * 128;
#pragma unroll
        for (int it = 0; it < 2; it++) {
            int row = lrow + it * 64;
            cp16(smem_u32(dh + row * SAB + lch * 8), ah + (size_t)row * 128 + lch * 8);
        }
    }
    CP_COMMIT();

    float acc[2][8][4];
#pragma unroll
    for (int mt = 0; mt < 2; mt++)
#pragma unroll
        for (int nt = 0; nt < 8; nt++)
#pragma unroll
            for (int j = 0; j < 4; j++) acc[mt][nt][j] = 0.0f;

#pragma unroll
    for (int c = 0; c < NC; c++) {
        CP_WAIT(0);
        __syncthreads();

        if (c + 1 < NC) {
            int nmt = (c + 1) >> 2, nkc = (c + 1) & 3;
            uint16_t* dh = Ast + ((c + 1) & 1) * PG_A_ELEMS;
            const uint16_t* ah = ahg + (size_t)(bm0 + (nmt << 7)) * 128 + nkc * 32;
#pragma unroll
            for (int it = 0; it < 2; it++) {
                int row = lrow + it * 64;
                cp16(smem_u32(dh + row * SAB + lch * 8), ah + (size_t)row * 128 + lch * 8);
            }
            CP_COMMIT();
        }

        uint16_t* Ah = Ast + (c & 1) * PG_A_ELEMS;
        const int kc = c & 3;

#pragma unroll
        for (int ks = 0; ks < 2; ks++) {
            int ac0 = ks * 16 + (seg >> 1) * 8;
            int bc0 = kc * 32 + ks * 16 + (seg & 1) * 8;
            uint32_t ahf[2][4];
#pragma unroll
            for (int mt = 0; mt < 2; mt++) {
                int row = warp_m * 32 + mt * 16 + lr + (seg & 1) * 8;
                LDSM_X4(ahf[mt], smem_u32(&Ah[row * SAB + ac0]));
            }
#pragma unroll
            for (int pg = 0; pg < 2; pg++) {
                uint32_t bhf2[2][4];
#pragma unroll
                for (int pi = 0; pi < 2; pi++) {
                    int row = warp_n * 64 + (2 * pg + pi) * 16 + lr + (seg >> 1) * 8;
                    LDSM_X4(bhf2[pi], smem_u32(&Bh[row * SBB + bc0]));
                }
                MMA_GROUP(4 * pg, ahf, bhf2);
            }
        }

        if (kc == 3) {
            int mt_i = c >> 2;
            int rbm = bm0 + (mt_i << 7);
            if (!LN) {
#pragma unroll
                for (int mt = 0; mt < 2; mt++) {
                    int r0 = rbm + warp_m * 32 + mt * 16 + g;
#pragma unroll
                    for (int nt = 0; nt < 8; nt++) {
                        int c0 = bn0 + warp_n * 64 + nt * 8 + tg * 2;
                        float b0 = bias[c0], b1 = bias[c0 + 1];
                        float v0 = acc[mt][nt][0] + b0;
                        float v1 = acc[mt][nt][1] + b1;
                        float v2 = acc[mt][nt][2] + b0;
                        float v3 = acc[mt][nt][3] + b1;
                        if (relu) {
                            v0 = fmaxf(v0, 0.0f); v1 = fmaxf(v1, 0.0f);
                            v2 = fmaxf(v2, 0.0f); v3 = fmaxf(v3, 0.0f);
                        }
                        if (Cf) {
                            *(float2*)(Cf + (size_t)r0 * N + c0)       = make_float2(v0, v1);
                            *(float2*)(Cf + (size_t)(r0 + 8) * N + c0) = make_float2(v2, v3);
                        }
                        if (Ch) {
                            *(uint32_t*)(Ch + (size_t)r0 * N + c0)       = pack_f16(v0, v1);
                            *(uint32_t*)(Ch + (size_t)(r0 + 8) * N + c0) = pack_f16(v2, v3);
                        }
                    }
                }
            } else {
#pragma unroll
                for (int mt = 0; mt < 2; mt++) {
#pragma unroll
                    for (int half = 0; half < 2; half++) {
                        int rl = warp_m * 32 + mt * 16 + g + half * 8;
                        float s = 0.0f, q = 0.0f;
#pragma unroll
                        for (int nt = 0; nt < 8; nt++) {
                            int c0 = warp_n * 64 + nt * 8 + tg * 2;
                            float2 rv = *(const float2*)(resid + (size_t)(rbm + rl) * 128 + c0);
                            float v0 = acc[mt][nt][2 * half]     + bias[c0]     + rv.x;
                            float v1 = acc[mt][nt][2 * half + 1] + bias[c0 + 1] + rv.y;
                            acc[mt][nt][2 * half]     = v0;
                            acc[mt][nt][2 * half + 1] = v1;
                            s += v0 + v1;
                            q += v0 * v0 + v1 * v1;
                        }
                        s += __shfl_xor_sync(0xffffffffu, s, 1);
                        q += __shfl_xor_sync(0xffffffffu, q, 1);
                        s += __shfl_xor_sync(0xffffffffu, s, 2);
                        q += __shfl_xor_sync(0xffffffffu, q, 2);
                        if (tg == 0) {
                            pS[rl * 2 + warp_n] = s;
                            pQ[rl * 2 + warp_n] = q;
                        }
                    }
                }
                __syncthreads();
#pragma unroll
                for (int mt = 0; mt < 2; mt++) {
#pragma unroll
                    for (int half = 0; half < 2; half++) {
                        int rl = warp_m * 32 + mt * 16 + g + half * 8;
                        float s = pS[rl * 2] + pS[rl * 2 + 1];
                        float q = pQ[rl * 2] + pQ[rl * 2 + 1];
                        float mu = s * (1.0f / 128.0f);
                        float var = q * (1.0f / 128.0f) - mu * mu;
                        float inv = rsqrtf(var + EPSV);
                        size_t rbase = (size_t)(rbm + rl) * 128;
#pragma unroll
                        for (int nt = 0; nt < 8; nt++) {
                            int c0 = warp_n * 64 + nt * 8 + tg * 2;
                            float v0 = (acc[mt][nt][2 * half]     - mu) * inv * lng[c0]     + lnb[c0];
                            float v1 = (acc[mt][nt][2 * half + 1] - mu) * inv * lng[c0 + 1] + lnb[c0 + 1];
                            *(float2*)(Cf + rbase + c0) = make_float2(v0, v1);
                            *(uint32_t*)(Ch + rbase + c0) = pack_f16(v0, v1);
                        }
                    }
                }
            }
#pragma unroll
            for (int mt = 0; mt < 2; mt++)
#pragma unroll
                for (int nt = 0; nt < 8; nt++)
#pragma unroll
                    for (int j = 0; j < 4; j++) acc[mt][nt][j] = 0.0f;
        }
    }
}

// ---------------- chunked GEMM (K=512 FF2, LN epilogue), single-term -------------
#define ARR_ELEMS (128 * SAB)
#define STAGE_ELEMS (2 * ARR_ELEMS)
#define GEMM_SMEM (2 * STAGE_ELEMS * 2)       // 40960 bytes
#define FF2_K 512

__global__ void __launch_bounds__(256, 3)
split_gemm_kernel(const __half* __restrict__ Ahg,
                  const __half* __restrict__ Bg,
                  const float* __restrict__ bias,
                  float* __restrict__ Cf,
                  __half* __restrict__ Ch,
                  const float* __restrict__ resid,
                  const float* __restrict__ lng, const float* __restrict__ lnb)
{
    extern __shared__ uint16_t smbuf[];

    int tid  = threadIdx.x;
    int wid  = tid >> 5;
    int lane = tid & 31;
    int g    = lane >> 2;
    int tg   = lane & 3;
    int lr   = lane & 7;
    int seg  = lane >> 3;
    int warp_m = wid & 3;
    int warp_n = wid >> 2;
    int bm0 = blockIdx.y * 128;

    const uint16_t* gbase[2];
    gbase[0] = (const uint16_t*)Ahg + (size_t)bm0 * FF2_K;
    gbase[1] = (const uint16_t*)Bg;

    int lrow = tid >> 2;
    int lch  = tid & 3;

    float acc[2][8][4];
#pragma unroll
    for (int mt = 0; mt < 2; mt++)
#pragma unroll
        for (int nt = 0; nt < 8; nt++)
#pragma unroll
            for (int j = 0; j < 4; j++) acc[mt][nt][j] = 0.0f;

    constexpr int nch = FF2_K >> 5;

    {
        uint16_t* st = smbuf;
#pragma unroll
        for (int arr = 0; arr < 2; arr++) {
            uint16_t* da = st + arr * ARR_ELEMS;
#pragma unroll
            for (int it = 0; it < 2; it++) {
                int row = lrow + it * 64;
                cp16(smem_u32(da + row * SAB + lch * 8),
                     gbase[arr] + (size_t)row * FF2_K + lch * 8);
            }
        }
    }
    CP_COMMIT();

#pragma unroll 4
    for (int kc = 0; kc < nch; kc++) {
        CP_WAIT(0);
        __syncthreads();

        if (kc + 1 < nch) {
            uint16_t* st = smbuf + ((kc + 1) & 1) * STAGE_ELEMS;
            int koff = (kc + 1) * 32;
#pragma unroll
            for (int arr = 0; arr < 2; arr++) {
                uint16_t* da = st + arr * ARR_ELEMS;
#pragma unroll
                for (int it = 0; it < 2; it++) {
                    int row = lrow + it * 64;
                    cp16(smem_u32(da + row * SAB + lch * 8),
                         gbase[arr] + (size_t)row * FF2_K + koff + lch * 8);
                }
            }
            CP_COMMIT();
        }

        uint16_t* st = smbuf + (kc & 1) * STAGE_ELEMS;
        uint16_t* Ah = st;
        uint16_t* Bh = st + ARR_ELEMS;

#pragma unroll
        for (int ks = 0; ks < 2; ks++) {
            int ac0 = ks * 16 + (seg >> 1) * 8;
            int bc0 = ks * 16 + (seg & 1) * 8;
            uint32_t ahf[2][4];
#pragma unroll
            for (int mt = 0; mt < 2; mt++) {
                int row = warp_m * 32 + mt * 16 + lr + (seg & 1) * 8;
                LDSM_X4(ahf[mt], smem_u32(&Ah[row * SAB + ac0]));
            }
#pragma unroll
            for (int pg = 0; pg < 2; pg++) {
                uint32_t bhf2[2][4];
#pragma unroll
                for (int pi = 0; pi < 2; pi++) {
                    int row = warp_n * 64 + (2 * pg + pi) * 16 + lr + (seg >> 1) * 8;
                    LDSM_X4(bhf2[pi], smem_u32(&Bh[row * SAB + bc0]));
                }
                MMA_GROUP(4 * pg, ahf, bhf2);
            }
        }
    }

    __syncthreads();
    float* pS = (float*)smbuf;
    float* pQ = pS + 256;

#pragma unroll
    for (int mt = 0; mt < 2; mt++) {
#pragma unroll
        for (int half = 0; half < 2; half++) {
            int rl = warp_m * 32 + mt * 16 + g + half * 8;
            float s = 0.0f, q = 0.0f;
#pragma unroll
            for (int nt = 0; nt < 8; nt++) {
                int c0 = warp_n * 64 + nt * 8 + tg * 2;
                float2 rv = *(const float2*)(resid + (size_t)(bm0 + rl) * 128 + c0);
                float v0 = acc[mt][nt][2 * half]     + bias[c0]     + rv.x;
                float v1 = acc[mt][nt][2 * half + 1] + bias[c0 + 1] + rv.y;
                acc[mt][nt][2 * half]     = v0;
                acc[mt][nt][2 * half + 1] = v1;
                s += v0 + v1;
                q += v0 * v0 + v1 * v1;
            }
            s += __shfl_xor_sync(0xffffffffu, s, 1);
            q += __shfl_xor_sync(0xffffffffu, q, 1);
            s += __shfl_xor_sync(0xffffffffu, s, 2);
            q += __shfl_xor_sync(0xffffffffu, q, 2);
            if (tg == 0) {
                pS[rl * 2 + warp_n] = s;
                pQ[rl * 2 + warp_n] = q;
            }
        }
    }
    __syncthreads();

#pragma unroll
    for (int mt = 0; mt < 2; mt++) {
#pragma unroll
        for (int half = 0; half < 2; half++) {
            int rl = warp_m * 32 + mt * 16 + g + half * 8;
            float s = pS[rl * 2] + pS[rl * 2 + 1];
            float q = pQ[rl * 2] + pQ[rl * 2 + 1];
            float mu = s * (1.0f / 128.0f);
            float var = q * (1.0f / 128.0f) - mu * mu;
            float inv = rsqrtf(var + EPSV);
            size_t rbase = (size_t)(bm0 + rl) * 128;
#pragma unroll
            for (int nt = 0; nt < 8; nt++) {
                int c0 = warp_n * 64 + nt * 8 + tg * 2;
                float v0 = (acc[mt][nt][2 * half]     - mu) * inv * lng[c0]     + lnb[c0];
                float v1 = (acc[mt][nt][2 * half + 1] - mu) * inv * lng[c0 + 1] + lnb[c0 + 1];
                *(float2*)(Cf + rbase + c0) = make_float2(v0, v1);
                *(uint32_t*)(Ch + rbase + c0) = pack_f16(v0, v1);
            }
        }
    }
}

// ---------------- weight convert+transpose kernels (fp16 single) -----------------
__global__ void wsplit_sq_kernel(const float* __restrict__ wq, const float* __restrict__ wk,
                                 const float* __restrict__ wv, const float* __restrict__ wo,
                                 const float* __restrict__ bq, const float* __restrict__ bk,
                                 const float* __restrict__ bv)
{
    int idx = blockIdx.x * blockDim.x + threadIdx.x;
    if (idx < L_ * 384) {
        int l = idx / 384, j = idx % 384;
        float v = (j < 128) ? bq[l * 128 + j] :
                  (j < 256) ? bk[l * 128 + j - 128] : bv[l * 128 + j - 256];
        d_bqkv[idx] = v;
    }
    if (idx >= L_ * 4 * 16384) return;
    int type = idx / (L_ * 16384);
    int rem  = idx % (L_ * 16384);
    int l    = rem / 16384;
    int kn   = rem % 16384;
    int k = kn >> 7, n = kn & 127;
    const float* src = (type == 0) ? wq : (type == 1) ? wk : (type == 2) ? wv : wo;
    float v = src[l * 16384 + k * 128 + n];
    int off = (type < 3) ? (l * 49152 + type * 16384 + n * 128 + k)
                         : (147456 + l * 16384 + n * 128 + k);
    d_wh[off] = __float2half_rn(v);
}

__global__ void wsplit_ff_kernel(const float* __restrict__ f1, const float* __restrict__ f2)
{
    int idx = blockIdx.x * blockDim.x + threadIdx.x;
    if (idx >= 2 * L_ * 65536) return;
    float v; int off;
    if (idx < L_ * 65536) {
        int l = idx / 65536, kn = idx % 65536;
        int k = kn >> 9, n = kn & 511;
        v = f1[l * 65536 + k * 512 + n];
        off = 196608 + l * 65536 + n * 128 + k;
    } else {
        int j = idx - L_ * 65536;
        int l = j / 65536, kn = j % 65536;
        int k = kn >> 7, n = kn & 127;
        v = f2[l * 65536 + k * 128 + n];
        off = 393216 + l * 65536 + n * 512 + k;
    }
    d_wh[off] = __float2half_rn(v);
}

// ---------------- hist projection + positional encoding --------------------------
__global__ void hist_pe_kernel(const float* __restrict__ feat,
                               const float* __restrict__ hw,
                               const float* __restrict__ hb)
{
    int idx = blockIdx.x * blockDim.x + threadIdx.x;
    if (idx >= R_ * D_) return;
    int row = idx >> 7;
    int d   = idx & 127;
    int t   = row & (T_ - 1);
    const float* f = feat + (size_t)row * 3;
    float xv = fmaf(f[0], hw[d],
               fmaf(f[1], hw[D_ + d],
               fmaf(f[2], hw[2 * D_ + d], hb[d])));
    d_x[idx] = xv;
    int j2 = d & ~1;
    float ang = (float)t * __expf(-9.210340371976184f * (float)j2 / 128.0f);
    float pe = (d & 1) ? __cosf(ang) : __sinf(ang);
    float oe = xv + pe;
    d_oute[idx] = oe;
    d_oute_h[idx] = __float2half_rn(oe);
}

// ---------------- fp16 tensor-core attention per (b,n,h) -------------------------
#define QK_STRIDE 24
#define VT_STRIDE 136

__global__ void __launch_bounds__(256)
attn_mma_kernel()
{
    int bn = blockIdx.x;
    int h  = blockIdx.y;

    __shared__ __half Qs[128 * QK_STRIDE];
    __shared__ __half Ks[128 * QK_STRIDE];
    __shared__ __half Vt[16 * VT_STRIDE];

    const float* base = d_qkv + (size_t)bn * T_ * 384;
    int tid = threadIdx.x;

    for (int i = tid; i < 2048; i += 256) {
        int r = i >> 4, c = i & 15;
        const float* rp = base + (size_t)r * 384 + h * 16 + c;
        Qs[r * QK_STRIDE + c] = __float2half_rn(rp[0] * 0.25f);
        Ks[r * QK_STRIDE + c] = __float2half_rn(rp[128]);
        Vt[c * VT_STRIDE + r] = __float2half_rn(rp[256]);
    }
    __syncthreads();

    int wid  = tid >> 5;
    int lane = tid & 31;
    int g    = lane >> 2;
    int tg   = lane & 3;
    int lr   = lane & 7;
    int seg  = lane >> 3;

    float S[16][4];
#pragma unroll
    for (int nt = 0; nt < 16; nt++)
#pragma unroll
        for (int j = 0; j < 4; j++) S[nt][j] = 0.0f;

    uint32_t qa[4];
    {
        int row = wid * 16 + lr + (seg & 1) * 8;
        int col = (seg >> 1) * 8;
        LDSM_X4(qa, smem_u32(&Qs[row * QK_STRIDE + col]));
    }
#pragma unroll
    for (int p = 0; p < 8; p++) {
        uint32_t kb[4];
        int row = p * 16 + lr + (seg >> 1) * 8;
        int col = (seg & 1) * 8;
        LDSM_X4(kb, smem_u32(&Ks[row * QK_STRIDE + col]));
        mma_f16(S[2 * p],     qa, kb[0], kb[1]);
        mma_f16(S[2 * p + 1], qa, kb[2], kb[3]);
    }

    float m0 = -INFINITY, m1 = -INFINITY;
#pragma unroll
    for (int nt = 0; nt < 16; nt++) {
        m0 = fmaxf(m0, fmaxf(S[nt][0], S[nt][1]));
        m1 = fmaxf(m1, fmaxf(S[nt][2], S[nt][3]));
    }
    m0 = fmaxf(m0, __shfl_xor_sync(0xffffffffu, m0, 1));
    m1 = fmaxf(m1, __shfl_xor_sync(0xffffffffu, m1, 1));
    m0 = fmaxf(m0, __shfl_xor_sync(0xffffffffu, m0, 2));
    m1 = fmaxf(m1, __shfl_xor_sync(0xffffffffu, m1, 2));

    float l0 = 0.0f, l1 = 0.0f;
#pragma unroll
    for (int nt = 0; nt < 16; nt++) {
        S[nt][0] = __expf(S[nt][0] - m0);
        S[nt][1] = __expf(S[nt][1] - m0);
        S[nt][2] = __expf(S[nt][2] - m1);
        S[nt][3] = __expf(S[nt][3] - m1);
        l0 += S[nt][0] + S[nt][1];
        l1 += S[nt][2] + S[nt][3];
    }
    l0 += __shfl_xor_sync(0xffffffffu, l0, 1);
    l1 += __shfl_xor_sync(0xffffffffu, l1, 1);
    l0 += __shfl_xor_sync(0xffffffffu, l0, 2);
    l1 += __shfl_xor_sync(0xffffffffu, l1, 2);

    float O[2][4];
#pragma unroll
    for (int nt = 0; nt < 2; nt++)
#pragma unroll
        for (int j = 0; j < 4; j++) O[nt][j] = 0.0f;

#pragma unroll
    for (int j = 0; j < 8; j++) {
        uint32_t pa[4];
        pa[0] = pack_f16(S[2 * j][0],     S[2 * j][1]);
        pa[1] = pack_f16(S[2 * j][2],     S[2 * j][3]);
        pa[2] = pack_f16(S[2 * j + 1][0], S[2 * j + 1][1]);
        pa[3] = pack_f16(S[2 * j + 1][2], S[2 * j + 1][3]);
        uint32_t vb[4];
        int row = lr + (seg >> 1) * 8;
        int col = j * 16 + (seg & 1) * 8;
        LDSM_X4(vb, smem_u32(&Vt[row * VT_STRIDE + col]));
        mma_f16(O[0], pa, vb[0], vb[1]);
        mma_f16(O[1], pa, vb[2], vb[3]);
    }

    float il0 = 1.0f / l0;
    float il1 = 1.0f / l1;
    size_t ro0 = (size_t)bn * T_ * D_ + (size_t)(wid * 16 + g) * D_ + h * 16;
    size_t ro1 = ro0 + 8 * D_;
#pragma unroll
    for (int nt = 0; nt < 2; nt++) {
        int d0 = nt * 8 + tg * 2;
        *(uint32_t*)(d_oh + ro0 + d0) = pack_f16(O[nt][0] * il0, O[nt][1] * il0);
        *(uint32_t*)(d_oh + ro1 + d0) = pack_f16(O[nt][2] * il1, O[nt][3] * il1);
    }
}

// ---------------- sdot + zero ----------------------------------------------------
__global__ void sdot_kernel()
{
    int gid = blockIdx.x * blockDim.x + threadIdx.x;
    int warp = gid >> 5;
    int lane = threadIdx.x & 31;
    if (gid < B_ * NN_) d_g[gid] = 0.0f;
    if (gid < 2) d_stats[gid] = 0.0;
    if (warp >= R_) return;
    size_t base = (size_t)warp * D_ + lane * 4;
    float4 w4 = *(const float4*)(d_oute + base);
    float4 x4 = *(const float4*)(d_x + base);
    float dt = w4.x * x4.x + w4.y * x4.y + w4.z * x4.z + w4.w * x4.w;
#pragma unroll
    for (int o = 16; o; o >>= 1) dt += __shfl_xor_sync(0xffffffffu, dt, o);
    if (lane == 0) {
        int b = warp / (NA_ * T_);
        int rem = warp % (NA_ * T_);
        int n = rem / T_;
        int t = rem % T_;
        d_s[b * NN_ + t * NA_ + n] = dt;
    }
}

// ---------------- edge aggregation ----------------------------------------------
__global__ void edge_kernel(const int* __restrict__ ei, const float* __restrict__ ew)
{
    int gid = blockIdx.x * blockDim.x + threadIdx.x;
    if (gid >= B_ * E_) return;
    int b = gid >> 16;
    int e = gid & (E_ - 1);
    const int* eb = ei + ((size_t)b << 17);
    int src = eb[e];
    int dst = eb[E_ + e];
    atomicAdd(&d_g[(b << 13) + dst], ew[((size_t)b << 16) + e] * d_s[(b << 13) + src]);
}

// ---------------- global batchnorm stats -----------------------------------------
__global__ void bnstats_kernel()
{
    double s = 0.0, sq = 0.0;
    for (int i = blockIdx.x * blockDim.x + threadIdx.x; i < B_ * NN_;
         i += gridDim.x * blockDim.x) {
        double v = (double)d_g[i];
        s += v; sq += v * v;
    }
#pragma unroll
    for (int o = 16; o; o >>= 1) {
        s  += __shfl_xor_sync(0xffffffffu, s, o);
        sq += __shfl_xor_sync(0xffffffffu, sq, o);
    }
    if ((threadIdx.x & 31) == 0) {
        atomicAdd(&d_stats[0], s);
        atomicAdd(&d_stats[1], sq);
    }
}

// ---------------- final outer product --------------------------------------------
__global__ void final_kernel(const float* __restrict__ bng, const float* __restrict__ bnb,
                             const float* __restrict__ lw, const float* __restrict__ lb,
                             float* __restrict__ out)
{
    int idx = blockIdx.x * blockDim.x + threadIdx.x;
    if (idx >= R_ * D_) return;
    int d   = idx & 127;
    int row = idx >> 7;
    int t   = row & 127;
    int bn  = row >> 7;
    int b   = bn >> 6;
    int n   = bn & 63;
    double mu  = d_stats[0] * (1.0 / 32768.0);
    double var = d_stats[1] * (1.0 / 32768.0) - mu * mu;
    float inv = rsqrtf((float)var + EPSV);
    float gval = d_g[b * NN_ + t * NA_ + n];
    float ghat = ((gval - (float)mu) * inv) * bng[0] + bnb[0];
    out[idx] = ghat * lw[d] + lb[d];
}

// ---------------- launcher -------------------------------------------------------
extern "C" void kernel_launch(void* const* d_in, const int* in_sizes, int n_in,
                              void* d_out, int out_size)
{
    const float* feat    = (const float*)d_in[0];
    const int*   eindex  = (const int*)  d_in[1];
    const float* eweight = (const float*)d_in[2];
    const float* hist_w  = (const float*)d_in[3];
    const float* hist_b  = (const float*)d_in[4];
    const float* wq      = (const float*)d_in[5];
    const float* bq      = (const float*)d_in[6];
    const float* wk      = (const float*)d_in[7];
    const float* bk      = (const float*)d_in[8];
    const float* wv      = (const float*)d_in[9];
    const float* bv      = (const float*)d_in[10];
    const float* wo      = (const float*)d_in[11];
    const float* bo      = (const float*)d_in[12];
    const float* ln1g    = (const float*)d_in[13];
    const float* ln1b    = (const float*)d_in[14];
    const float* fw1     = (const float*)d_in[15];
    const float* fb1     = (const float*)d_in[16];
    const float* fw2     = (const float*)d_in[17];
    const float* fb2     = (const float*)d_in[18];
    const float* ln2g    = (const float*)d_in[19];
    const float* ln2b    = (const float*)d_in[20];
    const float* bng     = (const float*)d_in[21];
    const float* bnb     = (const float*)d_in[22];
    const float* linw    = (const float*)d_in[23];
    const float* linb    = (const float*)d_in[24];
    float* out = (float*)d_out;

    float* pqkv = nullptr; cudaGetSymbolAddress((void**)&pqkv, d_qkv);
    float* poute = nullptr; cudaGetSymbolAddress((void**)&poute, d_oute);
    float* ph1  = nullptr; cudaGetSymbolAddress((void**)&ph1, d_h1);
    float* pbqkv = nullptr; cudaGetSymbolAddress((void**)&pbqkv, d_bqkv);

    __half *poute_h, *poh, *ph1h, *pffh, *pwh;
    cudaGetSymbolAddress((void**)&poute_h, d_oute_h);
    cudaGetSymbolAddress((void**)&poh,  d_oh);
    cudaGetSymbolAddress((void**)&ph1h, d_h1h);
    cudaGetSymbolAddress((void**)&pffh, d_ffh);
    cudaGetSymbolAddress((void**)&pwh,  d_wh);

    cudaFuncSetAttribute(split_gemm_kernel,
                         cudaFuncAttributeMaxDynamicSharedMemorySize, GEMM_SMEM);
    cudaFuncSetAttribute(pgemm_kernel<2, false>,
                         cudaFuncAttributeMaxDynamicSharedMemorySize, PG_SMEM);
    cudaFuncSetAttribute(pgemm_kernel<1, true>,
                         cudaFuncAttributeMaxDynamicSharedMemorySize, PG_SMEM);

    const int TPB = 256;

    // 0. weight convert+transpose
    wsplit_sq_kernel<<<(L_ * 4 * 16384 + TPB - 1) / TPB, TPB>>>(wq, wk, wv, wo, bq, bk, bv);
    wsplit_ff_kernel<<<(2 * L_ * 65536 + TPB - 1) / TPB, TPB>>>(fw1, fw2);

    // 1. x + positional encoding
    hist_pe_kernel<<<(R_ * D_ + TPB - 1) / TPB, TPB>>>(feat, hist_w, hist_b);

    // 2. transformer layers
    for (int l = 0; l < L_; l++) {
        const __half* wqkvh = pwh + l * 49152;
        const __half* woh = pwh + 147456 + l * 16384;
        const __half* f1h = pwh + 196608 + l * 65536;
        const __half* f2h = pwh + 393216 + l * 65536;

        // fused QKV (single-term)
        pgemm_kernel<2, false><<<dim3(3, 128), 256, PG_SMEM>>>(
            poute_h, wqkvh, pbqkv + l * 384,
            pqkv, nullptr, 384, 0, nullptr, nullptr, nullptr);

        // fp16 tensor-core attention
        attn_mma_kernel<<<dim3(B_ * NA_, H_), 256>>>();

        // O-proj + residual + LN1 -> h1
        pgemm_kernel<1, true><<<dim3(1, 256), 256, PG_SMEM>>>(
            poh, woh, bo + l * D_,
            ph1, ph1h, D_, 0, poute, ln1g + l * D_, ln1b + l * D_);

        // FFN-1 (ReLU)
        pgemm_kernel<2, false><<<dim3(4, 128), 256, PG_SMEM>>>(
            ph1h, f1h, fb1 + l * DFF_,
            nullptr, pffh, DFF_, 1, nullptr, nullptr, nullptr);

        // FFN-2 (K=512) + residual + LN2 -> oute
        split_gemm_kernel<<<dim3(1, 256), 256, GEMM_SMEM>>>(
            pffh, f2h, fb2 + l * D_,
            poute, poute_h, ph1, ln2g + l * D_, ln2b + l * D_);
    }

    // 3. scoring dot products (+ zero of d_g/d_stats)
    sdot_kernel<<<(R_ * 32 + TPB - 1) / TPB, TPB>>>();

    // 4. edge aggregation
    edge_kernel<<<(B_ * E_ + TPB - 1) / TPB, TPB>>>(eindex, eweight);

    // 5. global batchnorm stats + final outer product
    bnstats_kernel<<<64, TPB>>>();
    final_kernel<<<(R_ * D_ + TPB - 1) / TPB, TPB>>>(bng, bnb, linw, linb, out);
}

// round 17
// speedup vs baseline: 1.4885x; 1.4885x over previous
#include <cuda_runtime.h>
#include <cuda_bf16.h>
#include <cuda_fp16.h>
#include <cstdint>
#include <math.h>

// Problem constants
#define B_   4
#define NA_  64
#define T_   128
#define D_   128
#define H_   8
#define DH_  16
#define L_   3
#define DFF_ 512
#define E_   65536
#define NN_  (T_ * NA_)        // 8192
#define R_   (B_ * NA_ * T_)   // 32768 rows
#define EPSV 1e-5f

// ---------------- scratch (device globals) ---------------------------------------
__device__ __align__(256) float d_x   [R_ * D_];
__device__ __align__(256) float d_oute[R_ * D_];
__device__ __align__(256) float d_qkv [R_ * 384];
__device__ __align__(256) float d_h1  [R_ * D_];
__device__ __align__(256) float d_s   [B_ * NN_];
__device__ __align__(256) float d_g   [B_ * NN_];
__device__ double d_stats[2];

// fp16 activations (single term)
__device__ __align__(256) __half d_oute_h[R_ * D_];
__device__ __align__(256) __half d_oh[R_ * D_];
__device__ __align__(256) __half d_h1h[R_ * D_];
__device__ __align__(256) __half d_ffh[R_ * DFF_];

// fp16 transposed weights ([N][K])
#define W_TOT 589824
__device__ __align__(256) __half d_wh[W_TOT];
__device__ __align__(256) float d_bqkv[L_ * 384];

// ---------------- helpers --------------------------------------------------------
__device__ __forceinline__ uint32_t smem_u32(const void* p) {
    uint32_t a;
    asm("{ .reg .u64 t; cvta.to.shared.u64 t, %1; cvt.u32.u64 %0, t; }" : "=r"(a) : "l"(p));
    return a;
}
__device__ __forceinline__ void cp16(uint32_t saddr, const void* gptr) {
    asm volatile("cp.async.cg.shared.global [%0], [%1], 16;" :: "r"(saddr), "l"(gptr));
}
#define CP_COMMIT() asm volatile("cp.async.commit_group;" ::: "memory")
#define CP_WAIT(n)  asm volatile("cp.async.wait_group %0;" :: "n"(n) : "memory")

#define LDSM_X4(r, addr) \
    asm volatile("ldmatrix.sync.aligned.m8n8.x4.shared.b16 {%0,%1,%2,%3}, [%4];" \
        : "=r"((r)[0]), "=r"((r)[1]), "=r"((r)[2]), "=r"((r)[3]) : "r"(addr))

__device__ __forceinline__ uint32_t pack_f16(float a, float b) {
    __half2 h = __floats2half2_rn(a, b);
    return *(uint32_t*)&h;
}

__device__ __forceinline__ void mma_f16(float* c, const uint32_t* a,
                                        uint32_t b0, uint32_t b1) {
    asm volatile(
        "mma.sync.aligned.m16n8k16.row.col.f32.f16.f16.f32 "
        "{%0,%1,%2,%3}, {%4,%5,%6,%7}, {%8,%9}, {%0,%1,%2,%3};"
        : "+f"(c[0]), "+f"(c[1]), "+f"(c[2]), "+f"(c[3])
        : "r"(a[0]), "r"(a[1]), "r"(a[2]), "r"(a[3]), "r"(b0), "r"(b1));
}

#define SAB 40
#define SBB 136

// 8-MMA group over a p-pair (RAW distance 8)
#define MMA_GROUP(accbase, af, bhf2)                                               \
    do {                                                                            \
        _Pragma("unroll")                                                           \
        for (int pi = 0; pi < 2; pi++)                                              \
            _Pragma("unroll")                                                       \
            for (int hf = 0; hf < 2; hf++)                                          \
                _Pragma("unroll")                                                   \
                for (int mt = 0; mt < 2; mt++)                                      \
                    mma_f16(acc[mt][(accbase) + 2 * pi + hf], (af)[mt],             \
                            (bhf2)[pi][2 * hf], (bhf2)[pi][2 * hf + 1]);            \
    } while (0)

// ================= persistent-B GEMM (K=128), single-term fp16 ==================
#define PG_B_ELEMS (128 * SBB)                 // 17408
#define PG_A_ELEMS (128 * SAB)                 // 5120
#define PG_A_OFF   (PG_B_ELEMS)
#define PG_LN_OFF  (PG_A_OFF + 2 * PG_A_ELEMS) // 27648 elems
#define PG_SMEM    ((PG_LN_OFF) * 2 + 2048)    // 57344 bytes; occupancy capped at 2

template <int MT, bool LN>
__global__ void __launch_bounds__(256, 2)
pgemm_kernel(const __half* __restrict__ Ahg,
             const __half* __restrict__ Bg,
             const float* __restrict__ bias,
             float* __restrict__ Cf,
             __half* __restrict__ Ch,
             int N, int relu,
             const float* __restrict__ resid,
             const float* __restrict__ lng, const float* __restrict__ lnb)
{
    extern __shared__ uint16_t sm[];
    uint16_t* Bh = sm;
    uint16_t* Ast = sm + PG_A_OFF;
    float* pS = (float*)(sm + PG_LN_OFF);
    float* pQ = pS + 256;

    int tid  = threadIdx.x;
    int wid  = tid >> 5;
    int lane = tid & 31;
    int g    = lane >> 2;
    int tg   = lane & 3;
    int lr   = lane & 7;
    int seg  = lane >> 3;
    int warp_m = wid & 3;
    int warp_n = wid >> 2;
    int bn0 = blockIdx.x * 128;
    int bm0 = blockIdx.y * (MT << 7);

    // ---- load full B tile via cp.async ----
    {
        const uint16_t* bh = (const uint16_t*)Bg + (size_t)bn0 * 128;
#pragma unroll
        for (int it = 0; it < 8; it++) {
            int idx = it * 256 + tid;
            int row = idx >> 4, ch = idx & 15;
            cp16(smem_u32(Bh + row * SBB + ch * 8), bh + row * 128 + ch * 8);
        }
    }

    int lrow = tid >> 2;
    int lch  = tid & 3;

    const uint16_t* ahg = (const uint16_t*)Ahg;

    constexpr int NC = MT << 2;

    {
        uint16_t* dh = Ast;
        const uint16_t* ah = ahg + (size_t)bm0 * 128;
#pragma unroll
        for (int it = 0; it < 2; it++) {
            int row = lrow + it * 64;
            cp16(smem_u32(dh + row * SAB + lch * 8), ah + (size_t)row * 128 + lch * 8);
        }
    }
    CP_COMMIT();

    float acc[2][8][4];
#pragma unroll
    for (int mt = 0; mt < 2; mt++)
#pragma unroll
        for (int nt = 0; nt < 8; nt++)
#pragma unroll
            for (int j = 0; j < 4; j++) acc[mt][nt][j] = 0.0f;

#pragma unroll
    for (int c = 0; c < NC; c++) {
        CP_WAIT(0);
        __syncthreads();

        if (c + 1 < NC) {
            int nmt = (c + 1) >> 2, nkc = (c + 1) & 3;
            uint16_t* dh = Ast + ((c + 1) & 1) * PG_A_ELEMS;
            const uint16_t* ah = ahg + (size_t)(bm0 + (nmt << 7)) * 128 + nkc * 32;
#pragma unroll
            for (int it = 0; it < 2; it++) {
                int row = lrow + it * 64;
                cp16(smem_u32(dh + row * SAB + lch * 8), ah + (size_t)row * 128 + lch * 8);
            }
            CP_COMMIT();
        }

        uint16_t* Ah = Ast + (c & 1) * PG_A_ELEMS;
        const int kc = c & 3;

#pragma unroll
        for (int ks = 0; ks < 2; ks++) {
            int ac0 = ks * 16 + (seg >> 1) * 8;
            int bc0 = kc * 32 + ks * 16 + (seg & 1) * 8;
            uint32_t ahf[2][4];
#pragma unroll
            for (int mt = 0; mt < 2; mt++) {
                int row = warp_m * 32 + mt * 16 + lr + (seg & 1) * 8;
                LDSM_X4(ahf[mt], smem_u32(&Ah[row * SAB + ac0]));
            }
#pragma unroll
            for (int pg = 0; pg < 2; pg++) {
                uint32_t bhf2[2][4];
#pragma unroll
                for (int pi = 0; pi < 2; pi++) {
                    int row = warp_n * 64 + (2 * pg + pi) * 16 + lr + (seg >> 1) * 8;
                    LDSM_X4(bhf2[pi], smem_u32(&Bh[row * SBB + bc0]));
                }
                MMA_GROUP(4 * pg, ahf, bhf2);
            }
        }

        if (kc == 3) {
            int mt_i = c >> 2;
            int rbm = bm0 + (mt_i << 7);
            if (!LN) {
#pragma unroll
                for (int mt = 0; mt < 2; mt++) {
                    int r0 = rbm + warp_m * 32 + mt * 16 + g;
#pragma unroll
                    for (int nt = 0; nt < 8; nt++) {
                        int c0 = bn0 + warp_n * 64 + nt * 8 + tg * 2;
                        float b0 = bias[c0], b1 = bias[c0 + 1];
                        float v0 = acc[mt][nt][0] + b0;
                        float v1 = acc[mt][nt][1] + b1;
                        float v2 = acc[mt][nt][2] + b0;
                        float v3 = acc[mt][nt][3] + b1;
                        if (relu) {
                            v0 = fmaxf(v0, 0.0f); v1 = fmaxf(v1, 0.0f);
                            v2 = fmaxf(v2, 0.0f); v3 = fmaxf(v3, 0.0f);
                        }
                        if (Cf) {
                            *(float2*)(Cf + (size_t)r0 * N + c0)       = make_float2(v0, v1);
                            *(float2*)(Cf + (size_t)(r0 + 8) * N + c0) = make_float2(v2, v3);
                        }
                        if (Ch) {
                            *(uint32_t*)(Ch + (size_t)r0 * N + c0)       = pack_f16(v0, v1);
                            *(uint32_t*)(Ch + (size_t)(r0 + 8) * N + c0) = pack_f16(v2, v3);
                        }
                    }
                }
            } else {
#pragma unroll
                for (int mt = 0; mt < 2; mt++) {
#pragma unroll
                    for (int half = 0; half < 2; half++) {
                        int rl = warp_m * 32 + mt * 16 + g + half * 8;
                        float s = 0.0f, q = 0.0f;
#pragma unroll
                        for (int nt = 0; nt < 8; nt++) {
                            int c0 = warp_n * 64 + nt * 8 + tg * 2;
                            float2 rv = *(const float2*)(resid + (size_t)(rbm + rl) * 128 + c0);
                            float v0 = acc[mt][nt][2 * half]     + bias[c0]     + rv.x;
                            float v1 = acc[mt][nt][2 * half + 1] + bias[c0 + 1] + rv.y;
                            acc[mt][nt][2 * half]     = v0;
                            acc[mt][nt][2 * half + 1] = v1;
                            s += v0 + v1;
                            q += v0 * v0 + v1 * v1;
                        }
                        s += __shfl_xor_sync(0xffffffffu, s, 1);
                        q += __shfl_xor_sync(0xffffffffu, q, 1);
                        s += __shfl_xor_sync(0xffffffffu, s, 2);
                        q += __shfl_xor_sync(0xffffffffu, q, 2);
                        if (tg == 0) {
                            pS[rl * 2 + warp_n] = s;
                            pQ[rl * 2 + warp_n] = q;
                        }
                    }
                }
                __syncthreads();
#pragma unroll
                for (int mt = 0; mt < 2; mt++) {
#pragma unroll
                    for (int half = 0; half < 2; half++) {
                        int rl = warp_m * 32 + mt * 16 + g + half * 8;
                        float s = pS[rl * 2] + pS[rl * 2 + 1];
                        float q = pQ[rl * 2] + pQ[rl * 2 + 1];
                        float mu = s * (1.0f / 128.0f);
                        float var = q * (1.0f / 128.0f) - mu * mu;
                        float inv = rsqrtf(var + EPSV);
                        size_t rbase = (size_t)(rbm + rl) * 128;
#pragma unroll
                        for (int nt = 0; nt < 8; nt++) {
                            int c0 = warp_n * 64 + nt * 8 + tg * 2;
                            float v0 = (acc[mt][nt][2 * half]     - mu) * inv * lng[c0]     + lnb[c0];
                            float v1 = (acc[mt][nt][2 * half + 1] - mu) * inv * lng[c0 + 1] + lnb[c0 + 1];
                            *(float2*)(Cf + rbase + c0) = make_float2(v0, v1);
                            *(uint32_t*)(Ch + rbase + c0) = pack_f16(v0, v1);
                        }
                    }
                }
            }
#pragma unroll
            for (int mt = 0; mt < 2; mt++)
#pragma unroll
                for (int nt = 0; nt < 8; nt++)
#pragma unroll
                    for (int j = 0; j < 4; j++) acc[mt][nt][j] = 0.0f;
        }
    }
}

// ---------------- chunked GEMM (K=512 FF2, LN epilogue), single-term -------------
#define ARR_ELEMS (128 * SAB)
#define STAGE_ELEMS (2 * ARR_ELEMS)
#define GEMM_SMEM (2 * STAGE_ELEMS * 2)       // 40960 bytes
#define FF2_K 512

__global__ void __launch_bounds__(256, 2)
split_gemm_kernel(const __half* __restrict__ Ahg,
                  const __half* __restrict__ Bg,
                  const float* __restrict__ bias,
                  float* __restrict__ Cf,
                  __half* __restrict__ Ch,
                  const float* __restrict__ resid,
                  const float* __restrict__ lng, const float* __restrict__ lnb)
{
    extern __shared__ uint16_t smbuf[];

    int tid  = threadIdx.x;
    int wid  = tid >> 5;
    int lane = tid & 31;
    int g    = lane >> 2;
    int tg   = lane & 3;
    int lr   = lane & 7;
    int seg  = lane >> 3;
    int warp_m = wid & 3;
    int warp_n = wid >> 2;
    int bm0 = blockIdx.y * 128;

    const uint16_t* gbase[2];
    gbase[0] = (const uint16_t*)Ahg + (size_t)bm0 * FF2_K;
    gbase[1] = (const uint16_t*)Bg;

    int lrow = tid >> 2;
    int lch  = tid & 3;

    float acc[2][8][4];
#pragma unroll
    for (int mt = 0; mt < 2; mt++)
#pragma unroll
        for (int nt = 0; nt < 8; nt++)
#pragma unroll
            for (int j = 0; j < 4; j++) acc[mt][nt][j] = 0.0f;

    constexpr int nch = FF2_K >> 5;

    {
        uint16_t* st = smbuf;
#pragma unroll
        for (int arr = 0; arr < 2; arr++) {
            uint16_t* da = st + arr * ARR_ELEMS;
#pragma unroll
            for (int it = 0; it < 2; it++) {
                int row = lrow + it * 64;
                cp16(smem_u32(da + row * SAB + lch * 8),
                     gbase[arr] + (size_t)row * FF2_K + lch * 8);
            }
        }
    }
    CP_COMMIT();

#pragma unroll 4
    for (int kc = 0; kc < nch; kc++) {
        CP_WAIT(0);
        __syncthreads();

        if (kc + 1 < nch) {
            uint16_t* st = smbuf + ((kc + 1) & 1) * STAGE_ELEMS;
            int koff = (kc + 1) * 32;
#pragma unroll
            for (int arr = 0; arr < 2; arr++) {
                uint16_t* da = st + arr * ARR_ELEMS;
#pragma unroll
                for (int it = 0; it < 2; it++) {
                    int row = lrow + it * 64;
                    cp16(smem_u32(da + row * SAB + lch * 8),
                         gbase[arr] + (size_t)row * FF2_K + koff + lch * 8);
                }
            }
            CP_COMMIT();
        }

        uint16_t* st = smbuf + (kc & 1) * STAGE_ELEMS;
        uint16_t* Ah = st;
        uint16_t* Bh = st + ARR_ELEMS;

#pragma unroll
        for (int ks = 0; ks < 2; ks++) {
            int ac0 = ks * 16 + (seg >> 1) * 8;
            int bc0 = ks * 16 + (seg & 1) * 8;
            uint32_t ahf[2][4];
#pragma unroll
            for (int mt = 0; mt < 2; mt++) {
                int row = warp_m * 32 + mt * 16 + lr + (seg & 1) * 8;
                LDSM_X4(ahf[mt], smem_u32(&Ah[row * SAB + ac0]));
            }
#pragma unroll
            for (int pg = 0; pg < 2; pg++) {
                uint32_t bhf2[2][4];
#pragma unroll
                for (int pi = 0; pi < 2; pi++) {
                    int row = warp_n * 64 + (2 * pg + pi) * 16 + lr + (seg >> 1) * 8;
                    LDSM_X4(bhf2[pi], smem_u32(&Bh[row * SAB + bc0]));
                }
                MMA_GROUP(4 * pg, ahf, bhf2);
            }
        }
    }

    __syncthreads();
    float* pS = (float*)smbuf;
    float* pQ = pS + 256;

#pragma unroll
    for (int mt = 0; mt < 2; mt++) {
#pragma unroll
        for (int half = 0; half < 2; half++) {
            int rl = warp_m * 32 + mt * 16 + g + half * 8;
            float s = 0.0f, q = 0.0f;
#pragma unroll
            for (int nt = 0; nt < 8; nt++) {
                int c0 = warp_n * 64 + nt * 8 + tg * 2;
                float2 rv = *(const float2*)(resid + (size_t)(bm0 + rl) * 128 + c0);
                float v0 = acc[mt][nt][2 * half]     + bias[c0]     + rv.x;
                float v1 = acc[mt][nt][2 * half + 1] + bias[c0 + 1] + rv.y;
                acc[mt][nt][2 * half]     = v0;
                acc[mt][nt][2 * half + 1] = v1;
                s += v0 + v1;
                q += v0 * v0 + v1 * v1;
            }
            s += __shfl_xor_sync(0xffffffffu, s, 1);
            q += __shfl_xor_sync(0xffffffffu, q, 1);
            s += __shfl_xor_sync(0xffffffffu, s, 2);
            q += __shfl_xor_sync(0xffffffffu, q, 2);
            if (tg == 0) {
                pS[rl * 2 + warp_n] = s;
                pQ[rl * 2 + warp_n] = q;
            }
        }
    }
    __syncthreads();

#pragma unroll
    for (int mt = 0; mt < 2; mt++) {
#pragma unroll
        for (int half = 0; half < 2; half++) {
            int rl = warp_m * 32 + mt * 16 + g + half * 8;
            float s = pS[rl * 2] + pS[rl * 2 + 1];
            float q = pQ[rl * 2] + pQ[rl * 2 + 1];
            float mu = s * (1.0f / 128.0f);
            float var = q * (1.0f / 128.0f) - mu * mu;
            float inv = rsqrtf(var + EPSV);
            size_t rbase = (size_t)(bm0 + rl) * 128;
#pragma unroll
            for (int nt = 0; nt < 8; nt++) {
                int c0 = warp_n * 64 + nt * 8 + tg * 2;
                float v0 = (acc[mt][nt][2 * half]     - mu) * inv * lng[c0]     + lnb[c0];
                float v1 = (acc[mt][nt][2 * half + 1] - mu) * inv * lng[c0 + 1] + lnb[c0 + 1];
                *(float2*)(Cf + rbase + c0) = make_float2(v0, v1);
                *(uint32_t*)(Ch + rbase + c0) = pack_f16(v0, v1);
            }
        }
    }
}

// ---------------- weight convert+transpose kernels (fp16 single) -----------------
__global__ void wsplit_sq_kernel(const float* __restrict__ wq, const float* __restrict__ wk,
                                 const float* __restrict__ wv, const float* __restrict__ wo,
                                 const float* __restrict__ bq, const float* __restrict__ bk,
                                 const float* __restrict__ bv)
{
    int idx = blockIdx.x * blockDim.x + threadIdx.x;
    if (idx < L_ * 384) {
        int l = idx / 384, j = idx % 384;
        float v = (j < 128) ? bq[l * 128 + j] :
                  (j < 256) ? bk[l * 128 + j - 128] : bv[l * 128 + j - 256];
        d_bqkv[idx] = v;
    }
    if (idx >= L_ * 4 * 16384) return;
    int type = idx / (L_ * 16384);
    int rem  = idx % (L_ * 16384);
    int l    = rem / 16384;
    int kn   = rem % 16384;
    int k = kn >> 7, n = kn & 127;
    const float* src = (type == 0) ? wq : (type == 1) ? wk : (type == 2) ? wv : wo;
    float v = src[l * 16384 + k * 128 + n];
    int off = (type < 3) ? (l * 49152 + type * 16384 + n * 128 + k)
                         : (147456 + l * 16384 + n * 128 + k);
    d_wh[off] = __float2half_rn(v);
}

__global__ void wsplit_ff_kernel(const float* __restrict__ f1, const float* __restrict__ f2)
{
    int idx = blockIdx.x * blockDim.x + threadIdx.x;
    if (idx >= 2 * L_ * 65536) return;
    float v; int off;
    if (idx < L_ * 65536) {
        int l = idx / 65536, kn = idx % 65536;
        int k = kn >> 9, n = kn & 511;
        v = f1[l * 65536 + k * 512 + n];
        off = 196608 + l * 65536 + n * 128 + k;
    } else {
        int j = idx - L_ * 65536;
        int l = j / 65536, kn = j % 65536;
        int k = kn >> 7, n = kn & 127;
        v = f2[l * 65536 + k * 128 + n];
        off = 393216 + l * 65536 + n * 512 + k;
    }
    d_wh[off] = __float2half_rn(v);
}

// ---------------- hist projection + positional encoding --------------------------
__global__ void hist_pe_kernel(const float* __restrict__ feat,
                               const float* __restrict__ hw,
                               const float* __restrict__ hb)
{
    int idx = blockIdx.x * blockDim.x + threadIdx.x;
    if (idx >= R_ * D_) return;
    int row = idx >> 7;
    int d   = idx & 127;
    int t   = row & (T_ - 1);
    const float* f = feat + (size_t)row * 3;
    float xv = fmaf(f[0], hw[d],
               fmaf(f[1], hw[D_ + d],
               fmaf(f[2], hw[2 * D_ + d], hb[d])));
    d_x[idx] = xv;
    int j2 = d & ~1;
    float ang = (float)t * __expf(-9.210340371976184f * (float)j2 / 128.0f);
    float pe = (d & 1) ? __cosf(ang) : __sinf(ang);
    float oe = xv + pe;
    d_oute[idx] = oe;
    d_oute_h[idx] = __float2half_rn(oe);
}

// ---------------- fp16 tensor-core attention per (b,n,h) -------------------------
#define QK_STRIDE 24
#define VT_STRIDE 136

__global__ void __launch_bounds__(256)
attn_mma_kernel()
{
    int bn = blockIdx.x;
    int h  = blockIdx.y;

    __shared__ __half Qs[128 * QK_STRIDE];
    __shared__ __half Ks[128 * QK_STRIDE];
    __shared__ __half Vt[16 * VT_STRIDE];

    const float* base = d_qkv + (size_t)bn * T_ * 384;
    int tid = threadIdx.x;

    for (int i = tid; i < 2048; i += 256) {
        int r = i >> 4, c = i & 15;
        const float* rp = base + (size_t)r * 384 + h * 16 + c;
        Qs[r * QK_STRIDE + c] = __float2half_rn(rp[0] * 0.25f);
        Ks[r * QK_STRIDE + c] = __float2half_rn(rp[128]);
        Vt[c * VT_STRIDE + r] = __float2half_rn(rp[256]);
    }
    __syncthreads();

    int wid  = tid >> 5;
    int lane = tid & 31;
    int g    = lane >> 2;
    int tg   = lane & 3;
    int lr   = lane & 7;
    int seg  = lane >> 3;

    float S[16][4];
#pragma unroll
    for (int nt = 0; nt < 16; nt++)
#pragma unroll
        for (int j = 0; j < 4; j++) S[nt][j] = 0.0f;

    uint32_t qa[4];
    {
        int row = wid * 16 + lr + (seg & 1) * 8;
        int col = (seg >> 1) * 8;
        LDSM_X4(qa, smem_u32(&Qs[row * QK_STRIDE + col]));
    }
#pragma unroll
    for (int p = 0; p < 8; p++) {
        uint32_t kb[4];
        int row = p * 16 + lr + (seg >> 1) * 8;
        int col = (seg & 1) * 8;
        LDSM_X4(kb, smem_u32(&Ks[row * QK_STRIDE + col]));
        mma_f16(S[2 * p],     qa, kb[0], kb[1]);
        mma_f16(S[2 * p + 1], qa, kb[2], kb[3]);
    }

    float m0 = -INFINITY, m1 = -INFINITY;
#pragma unroll
    for (int nt = 0; nt < 16; nt++) {
        m0 = fmaxf(m0, fmaxf(S[nt][0], S[nt][1]));
        m1 = fmaxf(m1, fmaxf(S[nt][2], S[nt][3]));
    }
    m0 = fmaxf(m0, __shfl_xor_sync(0xffffffffu, m0, 1));
    m1 = fmaxf(m1, __shfl_xor_sync(0xffffffffu, m1, 1));
    m0 = fmaxf(m0, __shfl_xor_sync(0xffffffffu, m0, 2));
    m1 = fmaxf(m1, __shfl_xor_sync(0xffffffffu, m1, 2));

    float l0 = 0.0f, l1 = 0.0f;
#pragma unroll
    for (int nt = 0; nt < 16; nt++) {
        S[nt][0] = __expf(S[nt][0] - m0);
        S[nt][1] = __expf(S[nt][1] - m0);
        S[nt][2] = __expf(S[nt][2] - m1);
        S[nt][3] = __expf(S[nt][3] - m1);
        l0 += S[nt][0] + S[nt][1];
        l1 += S[nt][2] + S[nt][3];
    }
    l0 += __shfl_xor_sync(0xffffffffu, l0, 1);
    l1 += __shfl_xor_sync(0xffffffffu, l1, 1);
    l0 += __shfl_xor_sync(0xffffffffu, l0, 2);
    l1 += __shfl_xor_sync(0xffffffffu, l1, 2);

    float O[2][4];
#pragma unroll
    for (int nt = 0; nt < 2; nt++)
#pragma unroll
        for (int j = 0; j < 4; j++) O[nt][j] = 0.0f;

#pragma unroll
    for (int j = 0; j < 8; j++) {
        uint32_t pa[4];
        pa[0] = pack_f16(S[2 * j][0],     S[2 * j][1]);
        pa[1] = pack_f16(S[2 * j][2],     S[2 * j][3]);
        pa[2] = pack_f16(S[2 * j + 1][0], S[2 * j + 1][1]);
        pa[3] = pack_f16(S[2 * j + 1][2], S[2 * j + 1][3]);
        uint32_t vb[4];
        int row = lr + (seg >> 1) * 8;
        int col = j * 16 + (seg & 1) * 8;
        LDSM_X4(vb, smem_u32(&Vt[row * VT_STRIDE + col]));
        mma_f16(O[0], pa, vb[0], vb[1]);
        mma_f16(O[1], pa, vb[2], vb[3]);
    }

    float il0 = 1.0f / l0;
    float il1 = 1.0f / l1;
    size_t ro0 = (size_t)bn * T_ * D_ + (size_t)(wid * 16 + g) * D_ + h * 16;
    size_t ro1 = ro0 + 8 * D_;
#pragma unroll
    for (int nt = 0; nt < 2; nt++) {
        int d0 = nt * 8 + tg * 2;
        *(uint32_t*)(d_oh + ro0 + d0) = pack_f16(O[nt][0] * il0, O[nt][1] * il0);
        *(uint32_t*)(d_oh + ro1 + d0) = pack_f16(O[nt][2] * il1, O[nt][3] * il1);
    }
}

// ---------------- sdot + zero ----------------------------------------------------
__global__ void sdot_kernel()
{
    int gid = blockIdx.x * blockDim.x + threadIdx.x;
    int warp = gid >> 5;
    int lane = threadIdx.x & 31;
    if (gid < B_ * NN_) d_g[gid] = 0.0f;
    if (gid < 2) d_stats[gid] = 0.0;
    if (warp >= R_) return;
    size_t base = (size_t)warp * D_ + lane * 4;
    float4 w4 = *(const float4*)(d_oute + base);
    float4 x4 = *(const float4*)(d_x + base);
    float dt = w4.x * x4.x + w4.y * x4.y + w4.z * x4.z + w4.w * x4.w;
#pragma unroll
    for (int o = 16; o; o >>= 1) dt += __shfl_xor_sync(0xffffffffu, dt, o);
    if (lane == 0) {
        int b = warp / (NA_ * T_);
        int rem = warp % (NA_ * T_);
        int n = rem / T_;
        int t = rem % T_;
        d_s[b * NN_ + t * NA_ + n] = dt;
    }
}

// ---------------- edge aggregation ----------------------------------------------
__global__ void edge_kernel(const int* __restrict__ ei, const float* __restrict__ ew)
{
    int gid = blockIdx.x * blockDim.x + threadIdx.x;
    if (gid >= B_ * E_) return;
    int b = gid >> 16;
    int e = gid & (E_ - 1);
    const int* eb = ei + ((size_t)b << 17);
    int src = eb[e];
    int dst = eb[E_ + e];
    atomicAdd(&d_g[(b << 13) + dst], ew[((size_t)b << 16) + e] * d_s[(b << 13) + src]);
}

// ---------------- global batchnorm stats -----------------------------------------
__global__ void bnstats_kernel()
{
    double s = 0.0, sq = 0.0;
    for (int i = blockIdx.x * blockDim.x + threadIdx.x; i < B_ * NN_;
         i += gridDim.x * blockDim.x) {
        double v = (double)d_g[i];
        s += v; sq += v * v;
    }
#pragma unroll
    for (int o = 16; o; o >>= 1) {
        s  += __shfl_xor_sync(0xffffffffu, s, o);
        sq += __shfl_xor_sync(0xffffffffu, sq, o);
    }
    if ((threadIdx.x & 31) == 0) {
        atomicAdd(&d_stats[0], s);
        atomicAdd(&d_stats[1], sq);
    }
}

// ---------------- final outer product --------------------------------------------
__global__ void final_kernel(const float* __restrict__ bng, const float* __restrict__ bnb,
                             const float* __restrict__ lw, const float* __restrict__ lb,
                             float* __restrict__ out)
{
    int idx = blockIdx.x * blockDim.x + threadIdx.x;
    if (idx >= R_ * D_) return;
    int d   = idx & 127;
    int row = idx >> 7;
    int t   = row & 127;
    int bn  = row >> 7;
    int b   = bn >> 6;
    int n   = bn & 63;
    double mu  = d_stats[0] * (1.0 / 32768.0);
    double var = d_stats[1] * (1.0 / 32768.0) - mu * mu;
    float inv = rsqrtf((float)var + EPSV);
    float gval = d_g[b * NN_ + t * NA_ + n];
    float ghat = ((gval - (float)mu) * inv) * bng[0] + bnb[0];
    out[idx] = ghat * lw[d] + lb[d];
}

// ---------------- launcher -------------------------------------------------------
extern "C" void kernel_launch(void* const* d_in, const int* in_sizes, int n_in,
                              void* d_out, int out_size)
{
    const float* feat    = (const float*)d_in[0];
    const int*   eindex  = (const int*)  d_in[1];
    const float* eweight = (const float*)d_in[2];
    const float* hist_w  = (const float*)d_in[3];
    const float* hist_b  = (const float*)d_in[4];
    const float* wq      = (const float*)d_in[5];
    const float* bq      = (const float*)d_in[6];
    const float* wk      = (const float*)d_in[7];
    const float* bk      = (const float*)d_in[8];
    const float* wv      = (const float*)d_in[9];
    const float* bv      = (const float*)d_in[10];
    const float* wo      = (const float*)d_in[11];
    const float* bo      = (const float*)d_in[12];
    const float* ln1g    = (const float*)d_in[13];
    const float* ln1b    = (const float*)d_in[14];
    const float* fw1     = (const float*)d_in[15];
    const float* fb1     = (const float*)d_in[16];
    const float* fw2     = (const float*)d_in[17];
    const float* fb2     = (const float*)d_in[18];
    const float* ln2g    = (const float*)d_in[19];
    const float* ln2b    = (const float*)d_in[20];
    const float* bng     = (const float*)d_in[21];
    const float* bnb     = (const float*)d_in[22];
    const float* linw    = (const float*)d_in[23];
    const float* linb    = (const float*)d_in[24];
    float* out = (float*)d_out;

    float* pqkv = nullptr; cudaGetSymbolAddress((void**)&pqkv, d_qkv);
    float* poute = nullptr; cudaGetSymbolAddress((void**)&poute, d_oute);
    float* ph1  = nullptr; cudaGetSymbolAddress((void**)&ph1, d_h1);
    float* pbqkv = nullptr; cudaGetSymbolAddress((void**)&pbqkv, d_bqkv);

    __half *poute_h, *poh, *ph1h, *pffh, *pwh;
    cudaGetSymbolAddress((void**)&poute_h, d_oute_h);
    cudaGetSymbolAddress((void**)&poh,  d_oh);
    cudaGetSymbolAddress((void**)&ph1h, d_h1h);
    cudaGetSymbolAddress((void**)&pffh, d_ffh);
    cudaGetSymbolAddress((void**)&pwh,  d_wh);

    cudaFuncSetAttribute(split_gemm_kernel,
                         cudaFuncAttributeMaxDynamicSharedMemorySize, GEMM_SMEM);
    cudaFuncSetAttribute(pgemm_kernel<2, false>,
                         cudaFuncAttributeMaxDynamicSharedMemorySize, PG_SMEM);
    cudaFuncSetAttribute(pgemm_kernel<1, true>,
                         cudaFuncAttributeMaxDynamicSharedMemorySize, PG_SMEM);

    const int TPB = 256;

    // 0. weight convert+transpose
    wsplit_sq_kernel<<<(L_ * 4 * 16384 + TPB - 1) / TPB, TPB>>>(wq, wk, wv, wo, bq, bk, bv);
    wsplit_ff_kernel<<<(2 * L_ * 65536 + TPB - 1) / TPB, TPB>>>(fw1, fw2);

    // 1. x + positional encoding
    hist_pe_kernel<<<(R_ * D_ + TPB - 1) / TPB, TPB>>>(feat, hist_w, hist_b);

    // 2. transformer layers
    for (int l = 0; l < L_; l++) {
        const __half* wqkvh = pwh + l * 49152;
        const __half* woh = pwh + 147456 + l * 16384;
        const __half* f1h = pwh + 196608 + l * 65536;
        const __half* f2h = pwh + 393216 + l * 65536;

        // fused QKV (single-term)
        pgemm_kernel<2, false><<<dim3(3, 128), 256, PG_SMEM>>>(
            poute_h, wqkvh, pbqkv + l * 384,
            pqkv, nullptr, 384, 0, nullptr, nullptr, nullptr);

        // fp16 tensor-core attention
        attn_mma_kernel<<<dim3(B_ * NA_, H_), 256>>>();

        // O-proj + residual + LN1 -> h1
        pgemm_kernel<1, true><<<dim3(1, 256), 256, PG_SMEM>>>(
            poh, woh, bo + l * D_,
            ph1, ph1h, D_, 0, poute, ln1g + l * D_, ln1b + l * D_);

        // FFN-1 (ReLU)
        pgemm_kernel<2, false><<<dim3(4, 128), 256, PG_SMEM>>>(
            ph1h, f1h, fb1 + l * DFF_,
            nullptr, pffh, DFF_, 1, nullptr, nullptr, nullptr);

        // FFN-2 (K=512) + residual + LN2 -> oute
        split_gemm_kernel<<<dim3(1, 256), 256, GEMM_SMEM>>>(
            pffh, f2h, fb2 + l * D_,
            poute, poute_h, ph1, ln2g + l * D_, ln2b + l * D_);
    }

    // 3. scoring dot products (+ zero of d_g/d_stats)
    sdot_kernel<<<(R_ * 32 + TPB - 1) / TPB, TPB>>>();

    // 4. edge aggregation
    edge_kernel<<<(B_ * E_ + TPB - 1) / TPB, TPB>>>(eindex, eweight);

    // 5. global batchnorm stats + final outer product
    bnstats_kernel<<<64, TPB>>>();
    final_kernel<<<(R_ * D_ + TPB - 1) / TPB, TPB>>>(bng, bnb, linw, linb, out);
}